// round 1
// baseline (speedup 1.0000x reference)
#include <cuda_runtime.h>

#define Bn 4
#define Tn 2048
#define Cn 1024
#define Hn 16
#define Dn 64
#define Mn (Bn * Tn)

// Scratch (static __device__ arrays: allowed, no runtime alloc)
__device__ float g_qkv[(size_t)Mn * 3 * Cn];   // [8192, 3072]
__device__ float g_att[(size_t)Mn * Cn];       // [8192, 1024]

// ---------------------------------------------------------------------------
// SGEMM + bias:  C[M,N] = A[M,K] @ B[K,N] + bias[N]
// 128x128 block tile, BK=8, 256 threads, 8x8 per-thread (2x2 of 4x4 subtiles)
// ---------------------------------------------------------------------------
__global__ __launch_bounds__(256)
void sgemm_bias_kernel(const float* __restrict__ A,
                       const float* __restrict__ Bm,
                       const float* __restrict__ bias,
                       float* __restrict__ Cm,
                       int M, int N, int K)
{
    const int BK = 8;
    __shared__ float As[8][132];   // A tile transposed [k][m], padded
    __shared__ float Bs[8][128];   // B tile [k][n]

    const int tid  = threadIdx.x;
    const int tx   = tid & 15;
    const int ty   = tid >> 4;
    const int row0 = blockIdx.y * 128;
    const int col0 = blockIdx.x * 128;

    const int ar = tid >> 1;          // 0..127
    const int ac = (tid & 1) * 4;     // 0 or 4
    const int br = tid >> 5;          // 0..7
    const int bc = (tid & 31) * 4;    // 0..124

    const float* Ap = A  + (size_t)(row0 + ar) * K + ac;
    const float* Bp = Bm + (size_t)br * N + (col0 + bc);

    float acc[8][8];
#pragma unroll
    for (int i = 0; i < 8; i++)
#pragma unroll
        for (int j = 0; j < 8; j++) acc[i][j] = 0.0f;

    float4 a4 = *(const float4*)Ap;
    float4 b4 = *(const float4*)Bp;

    for (int k0 = 0; k0 < K; k0 += BK) {
        As[ac + 0][ar] = a4.x;
        As[ac + 1][ar] = a4.y;
        As[ac + 2][ar] = a4.z;
        As[ac + 3][ar] = a4.w;
        *(float4*)(&Bs[br][bc]) = b4;
        __syncthreads();

        if (k0 + BK < K) {   // prefetch next tiles while computing
            a4 = *(const float4*)(Ap + k0 + BK);
            b4 = *(const float4*)(Bp + (size_t)(k0 + BK) * N);
        }

#pragma unroll
        for (int k = 0; k < BK; k++) {
            float4 ra0 = *(const float4*)(&As[k][ty * 4]);
            float4 ra1 = *(const float4*)(&As[k][64 + ty * 4]);
            float4 rb0 = *(const float4*)(&Bs[k][tx * 4]);
            float4 rb1 = *(const float4*)(&Bs[k][64 + tx * 4]);
            float ra[8] = {ra0.x, ra0.y, ra0.z, ra0.w, ra1.x, ra1.y, ra1.z, ra1.w};
            float rb[8] = {rb0.x, rb0.y, rb0.z, rb0.w, rb1.x, rb1.y, rb1.z, rb1.w};
#pragma unroll
            for (int i = 0; i < 8; i++)
#pragma unroll
                for (int j = 0; j < 8; j++)
                    acc[i][j] = fmaf(ra[i], rb[j], acc[i][j]);
        }
        __syncthreads();
    }

#pragma unroll
    for (int ii = 0; ii < 2; ii++)
#pragma unroll
        for (int i = 0; i < 4; i++) {
            int r = row0 + ii * 64 + ty * 4 + i;
#pragma unroll
            for (int jj = 0; jj < 2; jj++) {
                int c = col0 + jj * 64 + tx * 4;
                float4 bv = *(const float4*)(&bias[c]);
                float4 ov;
                ov.x = acc[ii * 4 + i][jj * 4 + 0] + bv.x;
                ov.y = acc[ii * 4 + i][jj * 4 + 1] + bv.y;
                ov.z = acc[ii * 4 + i][jj * 4 + 2] + bv.z;
                ov.w = acc[ii * 4 + i][jj * 4 + 3] + bv.w;
                *(float4*)(&Cm[(size_t)r * N + c]) = ov;
            }
        }
}

// ---------------------------------------------------------------------------
// Flash attention, causal. One block = (batch*head, 64-row query tile).
// 128 threads: 16 (tx, kv/d cols) x 8 (ty, q rows), 8x4 fragment per thread.
// qkv layout: [B*T, 3C] row-major; q at col h*64, k at C + h*64, v at 2C + h*64
// ---------------------------------------------------------------------------
__global__ __launch_bounds__(128)
void attn_kernel(const float* __restrict__ qkv, float* __restrict__ att)
{
    __shared__ float Qs[64][64];  // [m][d ^ ((m&8)>>1)]  (half-warp bank split)
    __shared__ float KP[64][64];  // phase 1: Kt [d][n ^ d]; phase 2: P [m][k]
    __shared__ float Vs[64][64];  // [k][d]

    const int tid = threadIdx.x;
    const int tx  = tid & 15;
    const int ty  = tid >> 4;     // 0..7
    const int qt  = blockIdx.x;   // query tile 0..31
    const int bh  = blockIdx.y;   // 0..63
    const int b   = bh >> 4;
    const int h   = bh & 15;
    const int q0  = qt * 64;

    const float* base = qkv + (size_t)b * Tn * (3 * Cn);

    // Load Q tile (coalesced), swizzled store
    {
        const int r  = tid >> 4;          // 0..7
        const int d0 = (tid & 15) * 4;
#pragma unroll
        for (int mm = 0; mm < 8; mm++) {
            int m = mm * 8 + r;
            float4 q4 = *(const float4*)(base + (size_t)(q0 + m) * (3 * Cn) + h * 64 + d0);
            int dd = d0 ^ ((m & 8) >> 1);
            *(float4*)(&Qs[m][dd]) = q4;
        }
    }

    float o[8][4];
    float mrow[8], lrow[8];
#pragma unroll
    for (int i = 0; i < 8; i++) {
        mrow[i] = -1e30f;
        lrow[i] = 0.0f;
#pragma unroll
        for (int j = 0; j < 4; j++) o[i][j] = 0.0f;
    }

    const float scale = 0.125f;   // 1/sqrt(64)
    const int m0 = ty * 8;
    const int n0 = tx * 4;
    const int qswz = ((m0 & 8) >> 1);

    for (int t = 0; t <= qt; t++) {
        const int kv0 = t * 64;
        __syncthreads();   // prior-iter smem readers done (also covers Q store at t=0)

        // Load K (transposed + XOR-swizzled) and V
        {
            const int r  = tid >> 4;
            const int d0 = (tid & 15) * 4;
#pragma unroll
            for (int mm = 0; mm < 8; mm++) {
                int n = mm * 8 + r;
                const float* kp = base + (size_t)(kv0 + n) * (3 * Cn) + Cn + h * 64 + d0;
                float4 k4 = *(const float4*)kp;
                KP[d0 + 0][n ^ (d0 + 0)] = k4.x;
                KP[d0 + 1][n ^ (d0 + 1)] = k4.y;
                KP[d0 + 2][n ^ (d0 + 2)] = k4.z;
                KP[d0 + 3][n ^ (d0 + 3)] = k4.w;
                float4 v4 = *(const float4*)(kp + Cn);
                *(float4*)(&Vs[n][d0]) = v4;
            }
        }
        __syncthreads();

        // S = Q @ K^T  (8x4 fragment)
        float s[8][4];
#pragma unroll
        for (int i = 0; i < 8; i++)
#pragma unroll
            for (int j = 0; j < 4; j++) s[i][j] = 0.0f;

#pragma unroll 4
        for (int d = 0; d < 64; d++) {
            float kb[4];
#pragma unroll
            for (int j = 0; j < 4; j++)
                kb[j] = KP[d][(n0 + j) ^ d];
#pragma unroll
            for (int i = 0; i < 8; i++) {
                float qa = Qs[m0 + i][d ^ qswz];
#pragma unroll
                for (int j = 0; j < 4; j++)
                    s[i][j] = fmaf(qa, kb[j], s[i][j]);
            }
        }

        // scale + causal mask (only diagonal tile needs masking)
        if (t == qt) {
#pragma unroll
            for (int i = 0; i < 8; i++)
#pragma unroll
                for (int j = 0; j < 4; j++)
                    s[i][j] = (n0 + j > m0 + i) ? -1e30f : s[i][j] * scale;
        } else {
#pragma unroll
            for (int i = 0; i < 8; i++)
#pragma unroll
                for (int j = 0; j < 4; j++)
                    s[i][j] *= scale;
        }

        // online softmax per row (reduce over tx = lane bits 0..3)
#pragma unroll
        for (int i = 0; i < 8; i++) {
            float tm = fmaxf(fmaxf(s[i][0], s[i][1]), fmaxf(s[i][2], s[i][3]));
#pragma unroll
            for (int off = 8; off >= 1; off >>= 1)
                tm = fmaxf(tm, __shfl_xor_sync(0xffffffffu, tm, off));
            float mn   = fmaxf(mrow[i], tm);
            float corr = __expf(mrow[i] - mn);
            mrow[i] = mn;
            float rs = 0.0f;
#pragma unroll
            for (int j = 0; j < 4; j++) {
                float p = __expf(s[i][j] - mn);
                s[i][j] = p;
                rs += p;
            }
#pragma unroll
            for (int off = 8; off >= 1; off >>= 1)
                rs += __shfl_xor_sync(0xffffffffu, rs, off);
            lrow[i] = lrow[i] * corr + rs;
#pragma unroll
            for (int j = 0; j < 4; j++) o[i][j] *= corr;
        }

        __syncthreads();   // all done reading KP as Kt
        // write P into KP
#pragma unroll
        for (int i = 0; i < 8; i++)
            *(float4*)(&KP[m0 + i][n0]) = make_float4(s[i][0], s[i][1], s[i][2], s[i][3]);
        __syncthreads();

        // O += P @ V
#pragma unroll 4
        for (int k = 0; k < 64; k++) {
            float4 vb = *(const float4*)(&Vs[k][n0]);
#pragma unroll
            for (int i = 0; i < 8; i++) {
                float pa = KP[m0 + i][k];
                o[i][0] = fmaf(pa, vb.x, o[i][0]);
                o[i][1] = fmaf(pa, vb.y, o[i][1]);
                o[i][2] = fmaf(pa, vb.z, o[i][2]);
                o[i][3] = fmaf(pa, vb.w, o[i][3]);
            }
        }
    }

    // normalize + write out: att[b*T + r, h*64 + d]
#pragma unroll
    for (int i = 0; i < 8; i++) {
        float inv = 1.0f / lrow[i];
        int r = q0 + m0 + i;
        float4 ov = make_float4(o[i][0] * inv, o[i][1] * inv, o[i][2] * inv, o[i][3] * inv);
        *(float4*)(&att[((size_t)b * Tn + r) * Cn + h * 64 + n0]) = ov;
    }
}

// ---------------------------------------------------------------------------
extern "C" void kernel_launch(void* const* d_in, const int* in_sizes, int n_in,
                              void* d_out, int out_size)
{
    const float* x     = (const float*)d_in[0];  // [4,2048,1024]
    const float* Wqkv  = (const float*)d_in[1];  // [1024,3072]
    const float* bqkv  = (const float*)d_in[2];  // [3072]
    const float* Wproj = (const float*)d_in[3];  // [1024,1024]
    const float* bproj = (const float*)d_in[4];  // [1024]
    float* out = (float*)d_out;                  // [4,2048,1024]

    float *qkv_p = nullptr, *att_p = nullptr;
    cudaGetSymbolAddress((void**)&qkv_p, g_qkv);
    cudaGetSymbolAddress((void**)&att_p, g_att);

    // 1) QKV = X @ W_qkv + b_qkv
    sgemm_bias_kernel<<<dim3((3 * Cn) / 128, Mn / 128), 256>>>(
        x, Wqkv, bqkv, qkv_p, Mn, 3 * Cn, Cn);

    // 2) causal flash attention per (head, q-tile)
    attn_kernel<<<dim3(Tn / 64, Bn * Hn), 128>>>(qkv_p, att_p);

    // 3) out = att @ W_proj + b_proj
    sgemm_bias_kernel<<<dim3(Cn / 128, Mn / 128), 256>>>(
        att_p, Wproj, bproj, out, Mn, Cn, Cn);
}